// round 6
// baseline (speedup 1.0000x reference)
#include <cuda_runtime.h>
#include <math.h>

#define T_STEPS 256
#define B     64
#define DIN   512
#define H     1024
#define DOUT  512
#define G4    4096
#define NBLK  144
#define NTHR  256
#define LDA   68      // A rows: 272B, 16B aligned
#define LDW   136     // W rows (dup'd): 544B, 16B aligned
#define LDGS  66      // gate-park rows: 264B, 8B aligned

// ---------------- persistent state (allocation-free) ----------------
__device__ float g_h0[2][B*H];
__device__ float g_c0[B*H];
__device__ float g_h1[2][B*H];
__device__ float g_c1[B*H];

__device__ volatile unsigned g_gen;
__device__ unsigned          g_cnt;

__device__ __forceinline__ void grid_sync()
{
    __syncthreads();
    if (threadIdx.x == 0) {
        __threadfence();
        unsigned g = g_gen;
        if (atomicAdd(&g_cnt, 1u) == NBLK - 1u) {
            g_cnt = 0u;
            __threadfence();
            g_gen = g + 1u;
        } else {
            while (g_gen == g) { __nanosleep(40); }
        }
        __threadfence();
    }
    __syncthreads();
}

// packed dual-FMA: d.lo += a.lo*b.lo ; d.hi += a.hi*b.hi
#define FMA2(d, a, b) asm("fma.rn.f32x2 %0, %1, %2, %0;" : "+l"(d) : "l"(a), "l"(b))

__device__ __forceinline__ float lo32(unsigned long long v){ return __uint_as_float((unsigned)v); }
__device__ __forceinline__ float hi32(unsigned long long v){ return __uint_as_float((unsigned)(v >> 32)); }

// ================= gate stage (64 batches x 64 gate-cols per block) =========
struct GP { float4 a0, a1, w0, w1; };

__device__ __forceinline__ void gate_ld(GP& p, int kc, int KX,
    const float* __restrict__ X, int ldx,
    const float* __restrict__ Hp,
    const float* __restrict__ WX, const float* __restrict__ WH,
    int hid0, int tid)
{
    const bool inX = (kc < KX);
    {
        int b = tid >> 3, k4 = (tid & 7) * 4;
        p.a0 = inX ? *(const float4*)(X  + (size_t)b*ldx + kc + k4)
                   : *(const float4*)(Hp + (size_t)b*H   + (kc - KX) + k4);
    }
    {
        int f = tid + NTHR; int b = f >> 3, k4 = (f & 7) * 4;
        p.a1 = inX ? *(const float4*)(X  + (size_t)b*ldx + kc + k4)
                   : *(const float4*)(Hp + (size_t)b*H   + (kc - KX) + k4);
    }
    const float* W = inX ? WX : WH;
    const int krow = inX ? kc : (kc - KX);
    {
        int k = tid >> 4, cq = tid & 15;
        int g = cq >> 2, j4 = (cq & 3) * 4;
        p.w0 = *(const float4*)(W + (size_t)(krow + k)*G4 + g*H + hid0 + j4);
    }
    {
        int f = tid + NTHR; int k = f >> 4, cq = f & 15;
        int g = cq >> 2, j4 = (cq & 3) * 4;
        p.w1 = *(const float4*)(W + (size_t)(krow + k)*G4 + g*H + hid0 + j4);
    }
}

__device__ __forceinline__ void gate_st(const GP& p,
    float (*A)[LDA], float (*Wd)[LDW], int tid)
{
    {
        int b = tid >> 3, k4 = (tid & 7) * 4;
        A[k4+0][b] = p.a0.x; A[k4+1][b] = p.a0.y;
        A[k4+2][b] = p.a0.z; A[k4+3][b] = p.a0.w;
    }
    {
        int f = tid + NTHR; int b = f >> 3, k4 = (f & 7) * 4;
        A[k4+0][b] = p.a1.x; A[k4+1][b] = p.a1.y;
        A[k4+2][b] = p.a1.z; A[k4+3][b] = p.a1.w;
    }
    {
        int k = tid >> 4, cq = tid & 15;
        float4 d0 = make_float4(p.w0.x, p.w0.x, p.w0.y, p.w0.y);
        float4 d1 = make_float4(p.w0.z, p.w0.z, p.w0.w, p.w0.w);
        *(float4*)&Wd[k][8*cq    ] = d0;
        *(float4*)&Wd[k][8*cq + 4] = d1;
    }
    {
        int f = tid + NTHR; int k = f >> 4, cq = f & 15;
        float4 d0 = make_float4(p.w1.x, p.w1.x, p.w1.y, p.w1.y);
        float4 d1 = make_float4(p.w1.z, p.w1.z, p.w1.w, p.w1.w);
        *(float4*)&Wd[k][8*cq    ] = d0;
        *(float4*)&Wd[k][8*cq + 4] = d1;
    }
}

// 32-deep chunk: 3 LDS.128 + 8 FFMA2 per k per thread (16 FMA / 3 LDS)
__device__ __forceinline__ void gate_mm(const float (*A)[LDA], const float (*Wd)[LDW],
    int tx, int ty, unsigned long long* acc)
{
    #pragma unroll
    for (int k = 0; k < 32; ++k) {
        ulonglong2 av = *(const ulonglong2*)&A[k][4*ty];
        ulonglong2 wa = *(const ulonglong2*)&Wd[k][8*tx];
        ulonglong2 wb = *(const ulonglong2*)&Wd[k][8*tx + 4];
        FMA2(acc[0], av.x, wa.x); FMA2(acc[1], av.y, wa.x);
        FMA2(acc[2], av.x, wa.y); FMA2(acc[3], av.y, wa.y);
        FMA2(acc[4], av.x, wb.x); FMA2(acc[5], av.y, wb.x);
        FMA2(acc[6], av.x, wb.y); FMA2(acc[7], av.y, wb.y);
    }
}

__device__ void do_gate(int layer, int s,
    const float* __restrict__ inputs,
    const float* __restrict__ WX, const float* __restrict__ WH,
    const float* __restrict__ bias,
    int hid0,
    float (*A)[LDA], float (*Wd)[LDW], float (*Gs)[LDGS])
{
    const int tid = threadIdx.x;
    const int tx = tid & 15, ty = tid >> 4;

    const float* X; int KX, ldx; const float* Hp; float* cp; float* ho;
    if (layer == 0) {
        X  = inputs + (size_t)s * B * DIN; KX = DIN; ldx = DIN;
        Hp = g_h0[s & 1]; cp = g_c0; ho = g_h0[(s+1) & 1];
    } else {
        X  = g_h0[(s+1) & 1]; KX = H; ldx = H;
        Hp = g_h1[s & 1]; cp = g_c1; ho = g_h1[(s+1) & 1];
    }

    unsigned long long acc[8] = {0,0,0,0,0,0,0,0};
    const int nc = (KX + H) / 32;

    GP p;
    gate_ld(p, 0, KX, X, ldx, Hp, WX, WH, hid0, tid);
    gate_st(p, A, Wd, tid);
    __syncthreads();

    for (int c = 0; c < nc; ++c) {
        const bool more = (c + 1 < nc);
        if (more) gate_ld(p, (c+1)*32, KX, X, ldx, Hp, WX, WH, hid0, tid);
        gate_mm(A, Wd, tx, ty, acc);
        __syncthreads();
        if (more) { gate_st(p, A, Wd, tid); __syncthreads(); }
    }

    // park pre-activations (block-col = gate*16 + hid)
    #pragma unroll
    for (int q = 0; q < 4; ++q) {
        *(unsigned long long*)&Gs[4*tx + q][4*ty    ] = acc[q*2 + 0];
        *(unsigned long long*)&Gs[4*tx + q][4*ty + 2] = acc[q*2 + 1];
    }
    __syncthreads();

    #pragma unroll
    for (int j = 0; j < 4; ++j) {
        int item = tid + j * NTHR;        // 1024 (b, hid) pairs
        int b = item >> 4, hid = item & 15;
        int n = hid0 + hid;
        float gi = Gs[ 0 + hid][b] + bias[0*H + n];
        float gf = Gs[16 + hid][b] + bias[1*H + n];
        float gc = Gs[32 + hid][b] + bias[2*H + n];
        float go = Gs[48 + hid][b] + bias[3*H + n];
        float si = 1.f / (1.f + __expf(-gi));
        float sf = 1.f / (1.f + __expf(-gf));
        float so = 1.f / (1.f + __expf(-go));
        int idx = b * H + n;
        float cv = sf * cp[idx] + si * tanhf(gc);
        cp[idx] = cv;
        ho[idx] = so * tanhf(cv);
    }
}

// ================= output projection (64 batches x 32 cols per block) =======
struct PP { float4 a0, a1, w; };

__device__ __forceinline__ void proj_ld(PP& p, int kc,
    const float* __restrict__ h1, const float* __restrict__ Wout,
    int col0, int tid)
{
    { int b = tid >> 3, k4 = (tid & 7)*4;
      p.a0 = *(const float4*)(h1 + (size_t)b*H + kc + k4); }
    { int f = tid + NTHR; int b = f >> 3, k4 = (f & 7)*4;
      p.a1 = *(const float4*)(h1 + (size_t)b*H + kc + k4); }
    { int k = tid >> 3, cq = tid & 7;
      p.w = *(const float4*)(Wout + (size_t)(kc + k)*DOUT + col0 + 4*cq); }
}

__device__ __forceinline__ void proj_st(const PP& p,
    float (*A)[LDA], float (*Wd)[LDW], int tid)
{
    { int b = tid >> 3, k4 = (tid & 7)*4;
      A[k4+0][b] = p.a0.x; A[k4+1][b] = p.a0.y;
      A[k4+2][b] = p.a0.z; A[k4+3][b] = p.a0.w; }
    { int f = tid + NTHR; int b = f >> 3, k4 = (f & 7)*4;
      A[k4+0][b] = p.a1.x; A[k4+1][b] = p.a1.y;
      A[k4+2][b] = p.a1.z; A[k4+3][b] = p.a1.w; }
    { int k = tid >> 3, cq = tid & 7;
      float4 d0 = make_float4(p.w.x, p.w.x, p.w.y, p.w.y);
      float4 d1 = make_float4(p.w.z, p.w.z, p.w.w, p.w.w);
      *(float4*)&Wd[k][8*cq    ] = d0;
      *(float4*)&Wd[k][8*cq + 4] = d1; }
}

__device__ void do_proj(int s,
    const float* __restrict__ Wout, const float* __restrict__ bout,
    float* __restrict__ out, int col0,
    float (*A)[LDA], float (*Wd)[LDW])
{
    const int tid = threadIdx.x;
    const int tx = tid & 15, ty = tid >> 4;
    const float* h1 = g_h1[(s+1) & 1];

    unsigned long long acc[4] = {0,0,0,0};
    const int nc = H / 32;

    PP p;
    proj_ld(p, 0, h1, Wout, col0, tid);
    proj_st(p, A, Wd, tid);
    __syncthreads();

    for (int c = 0; c < nc; ++c) {
        const bool more = (c + 1 < nc);
        if (more) proj_ld(p, (c+1)*32, h1, Wout, col0, tid);
        #pragma unroll
        for (int k = 0; k < 32; ++k) {
            ulonglong2 av = *(const ulonglong2*)&A[k][4*ty];
            ulonglong2 wv = *(const ulonglong2*)&Wd[k][4*tx];
            FMA2(acc[0], av.x, wv.x); FMA2(acc[1], av.y, wv.x);
            FMA2(acc[2], av.x, wv.y); FMA2(acc[3], av.y, wv.y);
        }
        __syncthreads();
        if (more) { proj_st(p, A, Wd, tid); __syncthreads(); }
    }

    float* o = out + (size_t)s * B * DOUT;
    int cc = col0 + 2*tx;
    float bo0 = bout[cc], bo1 = bout[cc + 1];
    int b0 = 4*ty;
    o[(b0+0)*DOUT + cc    ] = lo32(acc[0]) + bo0;
    o[(b0+1)*DOUT + cc    ] = hi32(acc[0]) + bo0;
    o[(b0+2)*DOUT + cc    ] = lo32(acc[1]) + bo0;
    o[(b0+3)*DOUT + cc    ] = hi32(acc[1]) + bo0;
    o[(b0+0)*DOUT + cc + 1] = lo32(acc[2]) + bo1;
    o[(b0+1)*DOUT + cc + 1] = hi32(acc[2]) + bo1;
    o[(b0+2)*DOUT + cc + 1] = lo32(acc[3]) + bo1;
    o[(b0+3)*DOUT + cc + 1] = hi32(acc[3]) + bo1;
}

// ================= persistent pipelined kernel ==============================
__global__ __launch_bounds__(NTHR) void lstm_persistent(
    const float* __restrict__ inputs,
    const float* __restrict__ Wx0, const float* __restrict__ Wh0, const float* __restrict__ b0,
    const float* __restrict__ Wx1, const float* __restrict__ Wh1, const float* __restrict__ b1,
    const float* __restrict__ Wout, const float* __restrict__ bout,
    float* __restrict__ out)
{
    __shared__ __align__(16) float A [32][LDA];   //  8704 B
    __shared__ __align__(16) float Wd[32][LDW];   // 17408 B
    __shared__ __align__(16) float Gs[64][LDGS];  // 16896 B  (total 43008 B)

    const int bid = blockIdx.x;
    const int tid = threadIdx.x;

    for (int i = bid * NTHR + tid; i < B*H; i += NBLK * NTHR) {
        g_h0[0][i] = 0.f; g_h0[1][i] = 0.f; g_c0[i] = 0.f;
        g_h1[0][i] = 0.f; g_h1[1][i] = 0.f; g_c1[i] = 0.f;
    }
    grid_sync();

    // pipelined: phase t = { layer0(t) || layer1(t-1) || proj(t-2) }
    for (int t = 0; t < T_STEPS + 2; ++t) {
        if (bid < 64) {
            if (t < T_STEPS)
                do_gate(0, t, inputs, Wx0, Wh0, b0, bid * 16, A, Wd, Gs);
        } else if (bid < 128) {
            if (t >= 1 && t <= T_STEPS)
                do_gate(1, t - 1, nullptr, Wx1, Wh1, b1, (bid - 64) * 16, A, Wd, Gs);
        } else {
            if (t >= 2)
                do_proj(t - 2, Wout, bout, out, (bid - 128) * 32, A, Wd);
        }
        grid_sync();
    }

    // final (h, c) of layer 1: step T-1 wrote h1 buffer (T)&1 = 0
    float* dst = out + (size_t)T_STEPS * B * DOUT;
    for (int i = bid * NTHR + tid; i < B*H; i += NBLK * NTHR) {
        dst[i]       = g_h1[0][i];
        dst[B*H + i] = g_c1[i];
    }
}

extern "C" void kernel_launch(void* const* d_in, const int* in_sizes, int n_in,
                              void* d_out, int out_size)
{
    const float* inputs = (const float*)d_in[0];
    const float* Wx0    = (const float*)d_in[1];
    const float* Wh0    = (const float*)d_in[2];
    const float* b0     = (const float*)d_in[3];
    const float* Wx1    = (const float*)d_in[4];
    const float* Wh1    = (const float*)d_in[5];
    const float* b1     = (const float*)d_in[6];
    const float* Wout   = (const float*)d_in[7];
    const float* bout   = (const float*)d_in[8];
    float* out = (float*)d_out;

    lstm_persistent<<<NBLK, NTHR>>>(inputs, Wx0, Wh0, b0, Wx1, Wh1, b1,
                                    Wout, bout, out);
}